// round 3
// baseline (speedup 1.0000x reference)
#include <cuda_runtime.h>
#include <cuda_bf16.h>
#include <cstdint>

#define NFEAT 256
#define NDIM  128

#define NMAX  102400      // >= N_NODE + N_ATTRI = 102000
#define EMAX  1700000     // >= E = 1,600,000

// ---------------- CSR scratch (device globals; no allocation) ----------------
__device__ int   g_counts[2][NMAX + 1];
__device__ int   g_offs  [2][NMAX + 1];
__device__ int   g_cursor[2][NMAX + 1];
__device__ int   g_colp  [2][EMAX];
__device__ float g_valp  [2][EMAX];

// ---------------------------------------------------------------------------
// TF32 tensor-core GEMM (unchanged from R2): x1 = x0 @ W1^T
// ---------------------------------------------------------------------------
#define BM 64
#define BK 32
#define LDA 36

__device__ __forceinline__ unsigned f2tf32(float x) {
    unsigned r;
    asm("cvt.rna.tf32.f32 %0, %1;" : "=r"(r) : "f"(x));
    return r;
}

__device__ __forceinline__ void mma_tf32(float c[4],
                                         const unsigned a[4],
                                         unsigned b0, unsigned b1) {
    asm volatile(
        "mma.sync.aligned.m16n8k8.row.col.f32.tf32.tf32.f32 "
        "{%0,%1,%2,%3}, {%4,%5,%6,%7}, {%8,%9}, {%0,%1,%2,%3};\n"
        : "+f"(c[0]), "+f"(c[1]), "+f"(c[2]), "+f"(c[3])
        : "r"(a[0]), "r"(a[1]), "r"(a[2]), "r"(a[3]), "r"(b0), "r"(b1));
}

__global__ void __launch_bounds__(256)
gemm_tf32_kernel(const float* __restrict__ emb_node,
                 const float* __restrict__ emb_attri,
                 int n_node, int n_total,
                 const float* __restrict__ W1,
                 float* __restrict__ x1)
{
    __shared__ unsigned As[BM * LDA];
    __shared__ unsigned Ws[NDIM * LDA];

    const int tid  = threadIdx.x;
    const int lane = tid & 31;
    const int warp = tid >> 5;
    const int gid  = lane >> 2;
    const int tig  = lane & 3;
    const int wm   = warp & 1;
    const int wn   = warp >> 1;
    const int row0 = blockIdx.x * BM;

    float4 ra[2];
    float4 rw[4];

    auto ldg_chunk = [&](int k0) {
        #pragma unroll
        for (int i = 0; i < 2; i++) {
            int f = tid + 256 * i, r = f >> 3, u = f & 7;
            int grow = row0 + r;
            if (grow < n_total) {
                const float* src = (grow < n_node)
                    ? (emb_node  + (size_t)grow * NFEAT)
                    : (emb_attri + (size_t)(grow - n_node) * NFEAT);
                ra[i] = ((const float4*)(src + k0))[u];
            } else {
                ra[i] = make_float4(0.f, 0.f, 0.f, 0.f);
            }
        }
        #pragma unroll
        for (int i = 0; i < 4; i++) {
            int f = tid + 256 * i, r = f >> 3, u = f & 7;
            rw[i] = ((const float4*)(W1 + (size_t)r * NFEAT + k0))[u];
        }
    };

    auto sts_chunk = [&]() {
        #pragma unroll
        for (int i = 0; i < 2; i++) {
            int f = tid + 256 * i, r = f >> 3, u = f & 7;
            uint4 v = make_uint4(f2tf32(ra[i].x), f2tf32(ra[i].y),
                                 f2tf32(ra[i].z), f2tf32(ra[i].w));
            *(uint4*)&As[r * LDA + 4 * u] = v;
        }
        #pragma unroll
        for (int i = 0; i < 4; i++) {
            int f = tid + 256 * i, r = f >> 3, u = f & 7;
            uint4 v = make_uint4(f2tf32(rw[i].x), f2tf32(rw[i].y),
                                 f2tf32(rw[i].z), f2tf32(rw[i].w));
            *(uint4*)&Ws[r * LDA + 4 * u] = v;
        }
    };

    float c[2][4][4];
    #pragma unroll
    for (int mi = 0; mi < 2; mi++)
        #pragma unroll
        for (int ni = 0; ni < 4; ni++)
            #pragma unroll
            for (int q = 0; q < 4; q++) c[mi][ni][q] = 0.f;

    ldg_chunk(0);

    for (int ch = 0; ch < NFEAT / BK; ch++) {
        sts_chunk();
        __syncthreads();
        if (ch < NFEAT / BK - 1) ldg_chunk((ch + 1) * BK);

        #pragma unroll
        for (int s = 0; s < BK / 8; s++) {
            const int ks = s * 8;
            unsigned a[2][4];
            #pragma unroll
            for (int mi = 0; mi < 2; mi++) {
                int m = wm * 32 + mi * 16 + gid;
                a[mi][0] = As[m * LDA + ks + tig];
                a[mi][1] = As[(m + 8) * LDA + ks + tig];
                a[mi][2] = As[m * LDA + ks + tig + 4];
                a[mi][3] = As[(m + 8) * LDA + ks + tig + 4];
            }
            #pragma unroll
            for (int ni = 0; ni < 4; ni++) {
                int j = wn * 32 + ni * 8 + gid;
                unsigned b0 = Ws[j * LDA + ks + tig];
                unsigned b1 = Ws[j * LDA + ks + tig + 4];
                #pragma unroll
                for (int mi = 0; mi < 2; mi++)
                    mma_tf32(c[mi][ni], a[mi], b0, b1);
            }
        }
        __syncthreads();
    }

    #pragma unroll
    for (int mi = 0; mi < 2; mi++) {
        int r0 = row0 + wm * 32 + mi * 16 + gid;
        #pragma unroll
        for (int ni = 0; ni < 4; ni++) {
            int j = wn * 32 + ni * 8 + 2 * tig;
            if (r0 < n_total)
                *(float2*)(x1 + (size_t)r0 * NDIM + j) =
                    make_float2(c[mi][ni][0], c[mi][ni][1]);
            if (r0 + 8 < n_total)
                *(float2*)(x1 + (size_t)(r0 + 8) * NDIM + j) =
                    make_float2(c[mi][ni][2], c[mi][ni][3]);
        }
    }
}

// ---------------------------------------------------------------------------
// CSR build
// ---------------------------------------------------------------------------
__global__ void zero_counts_kernel(int n2) {
    int i = blockIdx.x * blockDim.x + threadIdx.x;
    int* p = &g_counts[0][0];
    if (i < n2) p[i] = 0;
}

__global__ void hist_kernel(int adj, const int* __restrict__ rows, int nedges) {
    int i = blockIdx.x * blockDim.x + threadIdx.x;
    if (i < nedges) atomicAdd(&g_counts[adj][rows[i]], 1);
}

// One block per adjacency (grid = 2). 1024 threads, each owns a contiguous
// chunk: local sum -> block scan -> write exclusive offsets + cursor copy.
__global__ void __launch_bounds__(1024)
scan_kernel(int n) {
    const int adj = blockIdx.x;
    const int* counts = g_counts[adj];
    int* offs   = g_offs[adj];
    int* cursor = g_cursor[adj];

    __shared__ int ssum[1024];
    const int tid = threadIdx.x;
    const int per = (n + 1023) >> 10;
    const int beg = tid * per;
    const int end = min(beg + per, n);

    int s = 0;
    for (int i = beg; i < end; i++) s += counts[i];
    ssum[tid] = s;
    __syncthreads();

    for (int d = 1; d < 1024; d <<= 1) {
        int t = (tid >= d) ? ssum[tid - d] : 0;
        __syncthreads();
        ssum[tid] += t;
        __syncthreads();
    }

    int off = ssum[tid] - s;   // exclusive prefix
    for (int i = beg; i < end; i++) {
        offs[i] = off;
        cursor[i] = off;
        off += counts[i];
    }
    if (end == n) offs[n] = off;   // total (identical value from all such threads)
}

__global__ void permute_kernel(int adj,
                               const int*   __restrict__ rows,
                               const int*   __restrict__ cols,
                               const float* __restrict__ vals,
                               int nedges) {
    int i = blockIdx.x * blockDim.x + threadIdx.x;
    if (i < nedges) {
        int r = rows[i];
        int p = atomicAdd(&g_cursor[adj][r], 1);
        g_colp[adj][p] = cols[i];
        g_valp[adj][p] = vals[i];
    }
}

// ---------------------------------------------------------------------------
// CSR SpMM (gather mode): out[r,:] = sum_e val[e] * x1[col[e],:]
// One warp per row; lane owns one float4 of the 128-dim row.
// Edge (col,val) distributed via shuffles; 4-way unrolled gathers for MLP.
// ---------------------------------------------------------------------------
__global__ void __launch_bounds__(256)
spmm_csr_kernel(int adj, const float* __restrict__ x1,
                float* __restrict__ out, int nrows)
{
    const int lane = threadIdx.x & 31;
    const int row  = blockIdx.x * 8 + (threadIdx.x >> 5);
    if (row >= nrows) return;

    const int* __restrict__ offs = g_offs[adj];
    const int* __restrict__ colp = g_colp[adj];
    const float* __restrict__ valp = g_valp[adj];

    const int beg = offs[row];
    const int end = offs[row + 1];

    float4 acc = make_float4(0.f, 0.f, 0.f, 0.f);

    for (int e = beg; e < end; e += 32) {
        const int idx = e + lane;
        int   c = 0;
        float v = 0.f;
        if (idx < end) { c = colp[idx]; v = valp[idx]; }
        const int cnt = min(32, end - e);

        int j = 0;
        for (; j + 4 <= cnt; j += 4) {
            int   c0 = __shfl_sync(0xffffffffu, c, j);
            int   c1 = __shfl_sync(0xffffffffu, c, j + 1);
            int   c2 = __shfl_sync(0xffffffffu, c, j + 2);
            int   c3 = __shfl_sync(0xffffffffu, c, j + 3);
            float v0 = __shfl_sync(0xffffffffu, v, j);
            float v1 = __shfl_sync(0xffffffffu, v, j + 1);
            float v2 = __shfl_sync(0xffffffffu, v, j + 2);
            float v3 = __shfl_sync(0xffffffffu, v, j + 3);
            float4 x0v = __ldg((const float4*)(x1 + (size_t)c0 * NDIM) + lane);
            float4 x1v = __ldg((const float4*)(x1 + (size_t)c1 * NDIM) + lane);
            float4 x2v = __ldg((const float4*)(x1 + (size_t)c2 * NDIM) + lane);
            float4 x3v = __ldg((const float4*)(x1 + (size_t)c3 * NDIM) + lane);
            acc.x += v0 * x0v.x; acc.y += v0 * x0v.y; acc.z += v0 * x0v.z; acc.w += v0 * x0v.w;
            acc.x += v1 * x1v.x; acc.y += v1 * x1v.y; acc.z += v1 * x1v.z; acc.w += v1 * x1v.w;
            acc.x += v2 * x2v.x; acc.y += v2 * x2v.y; acc.z += v2 * x2v.z; acc.w += v2 * x2v.w;
            acc.x += v3 * x3v.x; acc.y += v3 * x3v.y; acc.z += v3 * x3v.z; acc.w += v3 * x3v.w;
        }
        for (; j < cnt; j++) {
            int   cj = __shfl_sync(0xffffffffu, c, j);
            float vj = __shfl_sync(0xffffffffu, v, j);
            float4 xv = __ldg((const float4*)(x1 + (size_t)cj * NDIM) + lane);
            acc.x += vj * xv.x; acc.y += vj * xv.y; acc.z += vj * xv.z; acc.w += vj * xv.w;
        }
    }

    ((float4*)(out + (size_t)row * NDIM))[lane] = acc;
}

// ---------------------------------------------------------------------------
// kernel_launch
// ---------------------------------------------------------------------------
extern "C" void kernel_launch(void* const* d_in, const int* in_sizes, int n_in,
                              void* d_out, int out_size)
{
    const float* emb_node  = (const float*)d_in[0];
    const float* emb_attri = (const float*)d_in[1];
    const float* W1        = (const float*)d_in[2];
    const int*   a_row     = (const int*)d_in[3];
    const int*   a_col     = (const int*)d_in[4];
    const float* a_val     = (const float*)d_in[5];
    const int*   b_row     = (const int*)d_in[6];
    const int*   b_col     = (const int*)d_in[7];
    const float* b_val     = (const float*)d_in[8];

    const int n_node  = in_sizes[0] / NFEAT;
    const int n_attri = in_sizes[1] / NFEAT;
    const int n       = n_node + n_attri;
    const int E1      = in_sizes[3];
    const int E2      = in_sizes[6];

    float* x1 = (float*)d_out;
    float* x2 = x1 + (size_t)n * NDIM;
    float* x3 = x2 + (size_t)n * NDIM;

    // --- CSR build for both adjacencies ---
    // Note g_counts[0] and g_counts[1] are contiguous rows of one 2D array:
    // zero 2*(NMAX+1) covers both.
    const int n2 = 2 * (NMAX + 1);
    zero_counts_kernel<<<(n2 + 511) / 512, 512>>>(n2);
    hist_kernel<<<(E1 + 511) / 512, 512>>>(0, a_row, E1);
    hist_kernel<<<(E2 + 511) / 512, 512>>>(1, b_row, E2);
    scan_kernel<<<2, 1024>>>(n);
    permute_kernel<<<(E1 + 511) / 512, 512>>>(0, a_row, a_col, a_val, E1);
    permute_kernel<<<(E2 + 511) / 512, 512>>>(1, b_row, b_col, b_val, E2);

    // --- GEMM: x1 = x0 @ W1^T ---
    gemm_tf32_kernel<<<(n + BM - 1) / BM, 256>>>(
        emb_node, emb_attri, n_node, n, W1, x1);

    // --- SpMM (gather mode): every output row written exactly once ---
    spmm_csr_kernel<<<(n + 7) / 8, 256>>>(0, x1, x2, n);
    spmm_csr_kernel<<<(n + 7) / 8, 256>>>(1, x1, x3, n);
}

// round 4
// speedup vs baseline: 1.8646x; 1.8646x over previous
#include <cuda_runtime.h>
#include <cuda_fp16.h>
#include <cstdint>

#define NFEAT 256
#define NDIM  128

#define NMAX  102400      // >= N_NODE + N_ATTRI = 102000
#define EMAX  1700000     // >= E = 1,600,000
#define SCAN_CHUNK 512
#define NBLK_MAX ((NMAX + SCAN_CHUNK - 1) / SCAN_CHUNK)   // 200

// ---------------- CSR scratch (device globals; no allocation) ----------------
struct EdgeCV { int c; float v; };

__device__ int    g_counts[2][NMAX + 1];
__device__ int    g_offs  [2][NMAX + 1];
__device__ int    g_cursor[2][NMAX + 1];
__device__ EdgeCV g_edge  [2][EMAX];
__device__ int    g_bsums [2][NBLK_MAX];
__device__ int    g_bbase [2][NBLK_MAX];
__device__ __half g_x1h   [NMAX * NDIM];     // fp16 copy of x1 for gathers

// ---------------------------------------------------------------------------
// TF32 tensor-core GEMM: x1 = x0 @ W1^T  (+ fp16 shadow copy for SpMM gathers)
// ---------------------------------------------------------------------------
#define BM 64
#define BK 32
#define LDA 36

__device__ __forceinline__ unsigned f2tf32(float x) {
    unsigned r;
    asm("cvt.rna.tf32.f32 %0, %1;" : "=r"(r) : "f"(x));
    return r;
}

__device__ __forceinline__ void mma_tf32(float c[4],
                                         const unsigned a[4],
                                         unsigned b0, unsigned b1) {
    asm volatile(
        "mma.sync.aligned.m16n8k8.row.col.f32.tf32.tf32.f32 "
        "{%0,%1,%2,%3}, {%4,%5,%6,%7}, {%8,%9}, {%0,%1,%2,%3};\n"
        : "+f"(c[0]), "+f"(c[1]), "+f"(c[2]), "+f"(c[3])
        : "r"(a[0]), "r"(a[1]), "r"(a[2]), "r"(a[3]), "r"(b0), "r"(b1));
}

__global__ void __launch_bounds__(256)
gemm_tf32_kernel(const float* __restrict__ emb_node,
                 const float* __restrict__ emb_attri,
                 int n_node, int n_total,
                 const float* __restrict__ W1,
                 float* __restrict__ x1)
{
    __shared__ unsigned As[BM * LDA];
    __shared__ unsigned Ws[NDIM * LDA];

    const int tid  = threadIdx.x;
    const int lane = tid & 31;
    const int warp = tid >> 5;
    const int gid  = lane >> 2;
    const int tig  = lane & 3;
    const int wm   = warp & 1;
    const int wn   = warp >> 1;
    const int row0 = blockIdx.x * BM;

    float4 ra[2];
    float4 rw[4];

    auto ldg_chunk = [&](int k0) {
        #pragma unroll
        for (int i = 0; i < 2; i++) {
            int f = tid + 256 * i, r = f >> 3, u = f & 7;
            int grow = row0 + r;
            if (grow < n_total) {
                const float* src = (grow < n_node)
                    ? (emb_node  + (size_t)grow * NFEAT)
                    : (emb_attri + (size_t)(grow - n_node) * NFEAT);
                ra[i] = ((const float4*)(src + k0))[u];
            } else {
                ra[i] = make_float4(0.f, 0.f, 0.f, 0.f);
            }
        }
        #pragma unroll
        for (int i = 0; i < 4; i++) {
            int f = tid + 256 * i, r = f >> 3, u = f & 7;
            rw[i] = ((const float4*)(W1 + (size_t)r * NFEAT + k0))[u];
        }
    };

    auto sts_chunk = [&]() {
        #pragma unroll
        for (int i = 0; i < 2; i++) {
            int f = tid + 256 * i, r = f >> 3, u = f & 7;
            uint4 v = make_uint4(f2tf32(ra[i].x), f2tf32(ra[i].y),
                                 f2tf32(ra[i].z), f2tf32(ra[i].w));
            *(uint4*)&As[r * LDA + 4 * u] = v;
        }
        #pragma unroll
        for (int i = 0; i < 4; i++) {
            int f = tid + 256 * i, r = f >> 3, u = f & 7;
            uint4 v = make_uint4(f2tf32(rw[i].x), f2tf32(rw[i].y),
                                 f2tf32(rw[i].z), f2tf32(rw[i].w));
            *(uint4*)&Ws[r * LDA + 4 * u] = v;
        }
    };

    float c[2][4][4];
    #pragma unroll
    for (int mi = 0; mi < 2; mi++)
        #pragma unroll
        for (int ni = 0; ni < 4; ni++)
            #pragma unroll
            for (int q = 0; q < 4; q++) c[mi][ni][q] = 0.f;

    ldg_chunk(0);

    for (int ch = 0; ch < NFEAT / BK; ch++) {
        sts_chunk();
        __syncthreads();
        if (ch < NFEAT / BK - 1) ldg_chunk((ch + 1) * BK);

        #pragma unroll
        for (int s = 0; s < BK / 8; s++) {
            const int ks = s * 8;
            unsigned a[2][4];
            #pragma unroll
            for (int mi = 0; mi < 2; mi++) {
                int m = wm * 32 + mi * 16 + gid;
                a[mi][0] = As[m * LDA + ks + tig];
                a[mi][1] = As[(m + 8) * LDA + ks + tig];
                a[mi][2] = As[m * LDA + ks + tig + 4];
                a[mi][3] = As[(m + 8) * LDA + ks + tig + 4];
            }
            #pragma unroll
            for (int ni = 0; ni < 4; ni++) {
                int j = wn * 32 + ni * 8 + gid;
                unsigned b0 = Ws[j * LDA + ks + tig];
                unsigned b1 = Ws[j * LDA + ks + tig + 4];
                #pragma unroll
                for (int mi = 0; mi < 2; mi++)
                    mma_tf32(c[mi][ni], a[mi], b0, b1);
            }
        }
        __syncthreads();
    }

    #pragma unroll
    for (int mi = 0; mi < 2; mi++) {
        int r0 = row0 + wm * 32 + mi * 16 + gid;
        #pragma unroll
        for (int ni = 0; ni < 4; ni++) {
            int j = wn * 32 + ni * 8 + 2 * tig;
            float2 lo = make_float2(c[mi][ni][0], c[mi][ni][1]);
            float2 hi = make_float2(c[mi][ni][2], c[mi][ni][3]);
            if (r0 < n_total) {
                *(float2*)(x1 + (size_t)r0 * NDIM + j) = lo;
                *(__half2*)(g_x1h + (size_t)r0 * NDIM + j) = __float22half2_rn(lo);
            }
            if (r0 + 8 < n_total) {
                *(float2*)(x1 + (size_t)(r0 + 8) * NDIM + j) = hi;
                *(__half2*)(g_x1h + (size_t)(r0 + 8) * NDIM + j) = __float22half2_rn(hi);
            }
        }
    }
}

// ---------------------------------------------------------------------------
// CSR build: zero -> hist -> (block sums -> scan sums -> local scan) -> permute
// ---------------------------------------------------------------------------
__global__ void zero_counts_kernel(int n2) {
    int i = blockIdx.x * blockDim.x + threadIdx.x;
    int* p = &g_counts[0][0];
    if (i < n2) p[i] = 0;
}

__global__ void hist_kernel(int adj, const int* __restrict__ rows, int nedges) {
    int i = blockIdx.x * blockDim.x + threadIdx.x;
    if (i < nedges) atomicAdd(&g_counts[adj][rows[i]], 1);
}

// Phase 1: per-chunk sums. grid = (NBLK, 2), block = 512.
__global__ void __launch_bounds__(512)
scan_partial_kernel(int n) {
    const int adj = blockIdx.y;
    const int blk = blockIdx.x;
    const int tid = threadIdx.x;
    const int i = blk * SCAN_CHUNK + tid;
    int v = (i < n) ? g_counts[adj][i] : 0;

    // warp reduce, then cross-warp
    #pragma unroll
    for (int d = 16; d > 0; d >>= 1) v += __shfl_down_sync(0xffffffffu, v, d);
    __shared__ int ws[16];
    if ((tid & 31) == 0) ws[tid >> 5] = v;
    __syncthreads();
    if (tid < 16) {
        int s = ws[tid];
        #pragma unroll
        for (int d = 8; d > 0; d >>= 1) s += __shfl_down_sync(0xffffu, s, d);
        if (tid == 0) g_bsums[adj][blk] = s;
    }
}

// Phase 2: exclusive scan of block sums. grid = 2, block = 256 (NBLK <= 256).
__global__ void __launch_bounds__(256)
scan_sums_kernel(int nblk) {
    const int adj = blockIdx.x;
    const int tid = threadIdx.x;
    __shared__ int sm[256];
    int v = (tid < nblk) ? g_bsums[adj][tid] : 0;
    sm[tid] = v;
    __syncthreads();
    for (int d = 1; d < 256; d <<= 1) {
        int t = (tid >= d) ? sm[tid - d] : 0;
        __syncthreads();
        sm[tid] += t;
        __syncthreads();
    }
    if (tid < nblk) g_bbase[adj][tid] = sm[tid] - v;   // exclusive
}

// Phase 3: per-chunk local exclusive scan + base. grid = (NBLK, 2), block = 512.
__global__ void __launch_bounds__(512)
scan_local_kernel(int n) {
    const int adj = blockIdx.y;
    const int blk = blockIdx.x;
    const int tid = threadIdx.x;
    const int i = blk * SCAN_CHUNK + tid;
    int v = (i < n) ? g_counts[adj][i] : 0;

    __shared__ int sm[512];
    sm[tid] = v;
    __syncthreads();
    for (int d = 1; d < 512; d <<= 1) {
        int t = (tid >= d) ? sm[tid - d] : 0;
        __syncthreads();
        sm[tid] += t;
        __syncthreads();
    }
    const int incl = sm[tid];
    const int base = g_bbase[adj][blk];
    if (i < n) {
        int off = base + incl - v;
        g_offs[adj][i]   = off;
        g_cursor[adj][i] = off;
        if (i == n - 1) g_offs[adj][n] = base + incl;
    }
}

__global__ void permute_kernel(int adj,
                               const int*   __restrict__ rows,
                               const int*   __restrict__ cols,
                               const float* __restrict__ vals,
                               int nedges) {
    int i = blockIdx.x * blockDim.x + threadIdx.x;
    if (i < nedges) {
        int r = rows[i];
        int p = atomicAdd(&g_cursor[adj][r], 1);
        EdgeCV e; e.c = cols[i]; e.v = vals[i];
        g_edge[adj][p] = e;            // single 8B store
    }
}

// ---------------------------------------------------------------------------
// CSR SpMM (gather, fp16 source): out[r,:] = sum_e val[e] * x1h[col[e],:]
// One warp per row; lane owns 4 dims (8B fp16 per gather). fp32 accumulate.
// ---------------------------------------------------------------------------
__device__ __forceinline__ void acc_edge(float4& acc, float v, uint2 u) {
    float2 a = __half22float2(*(const __half2*)&u.x);
    float2 b = __half22float2(*(const __half2*)&u.y);
    acc.x += v * a.x; acc.y += v * a.y;
    acc.z += v * b.x; acc.w += v * b.y;
}

__global__ void __launch_bounds__(256)
spmm_csr_kernel(int adj, float* __restrict__ out, int nrows)
{
    const int lane = threadIdx.x & 31;
    const int row  = blockIdx.x * 8 + (threadIdx.x >> 5);
    if (row >= nrows) return;

    const int beg = g_offs[adj][row];
    const int end = g_offs[adj][row + 1];
    const EdgeCV* __restrict__ edges = g_edge[adj];

    float4 acc = make_float4(0.f, 0.f, 0.f, 0.f);

    for (int e = beg; e < end; e += 32) {
        const int idx = e + lane;
        int   c = 0;
        float v = 0.f;
        if (idx < end) {
            EdgeCV ecv = edges[idx];   // coalesced 8B
            c = ecv.c; v = ecv.v;
        }
        const int cnt = min(32, end - e);

        int j = 0;
        for (; j + 4 <= cnt; j += 4) {
            int   c0 = __shfl_sync(0xffffffffu, c, j);
            int   c1 = __shfl_sync(0xffffffffu, c, j + 1);
            int   c2 = __shfl_sync(0xffffffffu, c, j + 2);
            int   c3 = __shfl_sync(0xffffffffu, c, j + 3);
            float v0 = __shfl_sync(0xffffffffu, v, j);
            float v1 = __shfl_sync(0xffffffffu, v, j + 1);
            float v2 = __shfl_sync(0xffffffffu, v, j + 2);
            float v3 = __shfl_sync(0xffffffffu, v, j + 3);
            uint2 u0 = ((const uint2*)(g_x1h + (size_t)c0 * NDIM))[lane];
            uint2 u1 = ((const uint2*)(g_x1h + (size_t)c1 * NDIM))[lane];
            uint2 u2 = ((const uint2*)(g_x1h + (size_t)c2 * NDIM))[lane];
            uint2 u3 = ((const uint2*)(g_x1h + (size_t)c3 * NDIM))[lane];
            acc_edge(acc, v0, u0);
            acc_edge(acc, v1, u1);
            acc_edge(acc, v2, u2);
            acc_edge(acc, v3, u3);
        }
        for (; j < cnt; j++) {
            int   cj = __shfl_sync(0xffffffffu, c, j);
            float vj = __shfl_sync(0xffffffffu, v, j);
            uint2 uj = ((const uint2*)(g_x1h + (size_t)cj * NDIM))[lane];
            acc_edge(acc, vj, uj);
        }
    }

    ((float4*)(out + (size_t)row * NDIM))[lane] = acc;
}

// ---------------------------------------------------------------------------
// kernel_launch
// ---------------------------------------------------------------------------
extern "C" void kernel_launch(void* const* d_in, const int* in_sizes, int n_in,
                              void* d_out, int out_size)
{
    const float* emb_node  = (const float*)d_in[0];
    const float* emb_attri = (const float*)d_in[1];
    const float* W1        = (const float*)d_in[2];
    const int*   a_row     = (const int*)d_in[3];
    const int*   a_col     = (const int*)d_in[4];
    const float* a_val     = (const float*)d_in[5];
    const int*   b_row     = (const int*)d_in[6];
    const int*   b_col     = (const int*)d_in[7];
    const float* b_val     = (const float*)d_in[8];

    const int n_node  = in_sizes[0] / NFEAT;
    const int n_attri = in_sizes[1] / NFEAT;
    const int n       = n_node + n_attri;
    const int E1      = in_sizes[3];
    const int E2      = in_sizes[6];

    float* x1 = (float*)d_out;
    float* x2 = x1 + (size_t)n * NDIM;
    float* x3 = x2 + (size_t)n * NDIM;

    const int nblk = (n + SCAN_CHUNK - 1) / SCAN_CHUNK;

    // --- CSR build (both adjacencies) ---
    const int n2 = 2 * (NMAX + 1);
    zero_counts_kernel<<<(n2 + 511) / 512, 512>>>(n2);
    hist_kernel<<<(E1 + 511) / 512, 512>>>(0, a_row, E1);
    hist_kernel<<<(E2 + 511) / 512, 512>>>(1, b_row, E2);
    scan_partial_kernel<<<dim3(nblk, 2), 512>>>(n);
    scan_sums_kernel<<<2, 256>>>(nblk);
    scan_local_kernel<<<dim3(nblk, 2), 512>>>(n);
    permute_kernel<<<(E1 + 511) / 512, 512>>>(0, a_row, a_col, a_val, E1);
    permute_kernel<<<(E2 + 511) / 512, 512>>>(1, b_row, b_col, b_val, E2);

    // --- GEMM: x1 = x0 @ W1^T (also writes fp16 shadow) ---
    gemm_tf32_kernel<<<(n + BM - 1) / BM, 256>>>(
        emb_node, emb_attri, n_node, n, W1, x1);

    // --- SpMM (gather mode, fp16 source): each row written exactly once ---
    spmm_csr_kernel<<<(n + 7) / 8, 256>>>(0, x2, n);
    spmm_csr_kernel<<<(n + 7) / 8, 256>>>(1, x3, n);
}